// round 17
// baseline (speedup 1.0000x reference)
#include <cuda_runtime.h>
#include <cuda_bf16.h>
#include <cstdint>
#include <cstddef>

// Problem constants (fixed by the dataset)
#define KCODES   8192
#define DDIM     512
#define NROWS    32768        // B*N = 8*4096
#define BND_ELEMS 16777216ULL // B*N*D

// int8 GEMM tiling
#define TM 128
#define TN 128
#define BK 64                 // 64 s8 per chunk = two k32 mma steps
#define NCHUNK (DDIM / BK)    // 8
#define ROWPB 80              // smem row pitch in BYTES (64B data + 16B pad)
#define STAGES 4
#define ABUF (TM * ROWPB)     // 10240 B per stage per matrix
#define A_BYTES (STAGES * ABUF)
#define B_BYTES (STAGES * ABUF)
#define SMEM_MMA (A_BYTES + B_BYTES + TM * 16 + TM * 4)
#define CSLOTS 512

// Scratch (no cudaMalloc allowed). Only touched from device code.
__device__ unsigned long long g_minpair[NROWS];
__device__ float g_cbsq[KCODES];
__device__ float g_xsq[NROWS];
__device__ float g_amin[NROWS];
__device__ int   g_cnt[NROWS];
__device__ int   g_ovf[NROWS];
__device__ unsigned long long g_cand[(size_t)NROWS * CSLOTS];
__device__ int8_t g_zq[(size_t)NROWS * DDIM];
__device__ int8_t g_cbq[(size_t)KCODES * DDIM];
__device__ float g_sx[NROWS];     // per-row x quant scale
__device__ float g_sax[NROWS];    // per-row sum |x|
__device__ float g_sc[KCODES];    // per-code c quant scale
__device__ float g_marg[NROWS];   // per-row guaranteed margin
__device__ unsigned int g_ecmax_bits;   // max_k sc_k (float bits)
__device__ unsigned int g_csum_bits;    // max_k sum|c_k| (float bits)

// ---------------------------------------------------------------------------
// helpers
// ---------------------------------------------------------------------------
__device__ __forceinline__ uint32_t smem_to_u32(const void* p) {
    uint32_t a;
    asm("{ .reg .u64 t; cvta.to.shared.u64 t, %1; cvt.u32.u64 %0, t; }"
        : "=r"(a) : "l"(p));
    return a;
}

__device__ __forceinline__ unsigned int forder(float f) {
    unsigned int u = __float_as_uint(f);
    return (u & 0x80000000u) ? ~u : (u | 0x80000000u);
}

__device__ __forceinline__ void cp16(uint32_t saddr, const void* gptr) {
    asm volatile("cp.async.cg.shared.global [%0], [%1], 16;"
                 :: "r"(saddr), "l"(gptr));
}

__device__ __forceinline__ void ldmx4(uint32_t& r0, uint32_t& r1,
                                      uint32_t& r2, uint32_t& r3, uint32_t addr) {
    asm volatile("ldmatrix.sync.aligned.m8n8.x4.shared.b16 {%0,%1,%2,%3}, [%4];"
                 : "=r"(r0), "=r"(r1), "=r"(r2), "=r"(r3) : "r"(addr));
}

// s8 mma: D(s32) += A(16x32 s8) * B(8x32 s8)^T
__device__ __forceinline__ void mma16832(int* d, const uint32_t* a,
                                         const uint32_t* b) {
    asm volatile(
        "mma.sync.aligned.m16n8k32.row.col.s32.s8.s8.s32 "
        "{%0,%1,%2,%3}, {%4,%5,%6,%7}, {%8,%9}, {%0,%1,%2,%3};"
        : "+r"(d[0]), "+r"(d[1]), "+r"(d[2]), "+r"(d[3])
        : "r"(a[0]), "r"(a[1]), "r"(a[2]), "r"(a[3]), "r"(b[0]), "r"(b[1]));
}

// exact sequential fp32 dot + reference rounding chain -> packed score|k
__device__ __forceinline__ unsigned long long exact_pack(const float* __restrict__ zr,
                                                         const float* __restrict__ cbr,
                                                         int row, int k) {
    float acc = 0.0f;
    #pragma unroll 8
    for (int d = 0; d < DDIM; d += 4) {
        float4 a = *reinterpret_cast<const float4*>(zr + d);
        float4 b = *reinterpret_cast<const float4*>(cbr + d);
        acc = __fmaf_rn(a.x, b.x, acc);
        acc = __fmaf_rn(a.y, b.y, acc);
        acc = __fmaf_rn(a.z, b.z, acc);
        acc = __fmaf_rn(a.w, b.w, acc);
    }
    float t = __fadd_rn(g_cbsq[k], g_xsq[row]);
    float s = __fadd_rn(t, __fmul_rn(2.0f, acc));
    return ((unsigned long long)forder(s) << 32) | (unsigned int)k;
}

// issue one BK-chunk of A and B into stage buffer stg via cp.async
__device__ __forceinline__ void issue_stage(uint32_t AbaseS, uint32_t BbaseS,
                                            int tid, int m0, int k0,
                                            int stg, int ch) {
    #pragma unroll
    for (int t = 0; t < 2; t++) {
        int u = tid + t * 256;
        int row = u >> 2, seg = u & 3;          // 4 x 16B per 64B row
        uint32_t off = (uint32_t)stg * ABUF + (uint32_t)(row * ROWPB + seg * 16);
        cp16(AbaseS + off, &g_zq[(size_t)(m0 + row) * DDIM + ch * BK + seg * 16]);
        cp16(BbaseS + off, &g_cbq[(size_t)(k0 + row) * DDIM + ch * BK + seg * 16]);
    }
    asm volatile("cp.async.commit_group;");
}

// ---------------------------------------------------------------------------
// kernel 0: reset per-replay state
// ---------------------------------------------------------------------------
__global__ void vq_init_kernel() {
    int i = blockIdx.x * blockDim.x + threadIdx.x;
    if (i < NROWS) {
        g_minpair[i] = 0xFFFFFFFFFFFFFFFFULL;
        g_amin[i] = __int_as_float(0x7F800000);  // +inf
        g_cnt[i] = 0;
        g_ovf[i] = 0;
    }
    if (i == 0) { g_ecmax_bits = 0; g_csum_bits = 0; }
}

// ---------------------------------------------------------------------------
// kernel 1: squared norms, STRICTLY SEQUENTIAL fp32: s = fl(s + fl(v*v)).
// ---------------------------------------------------------------------------
__device__ __forceinline__ float sqsum_row_body(const float* __restrict__ src,
                                                float tile[128][33], int tid,
                                                int r0) {
    float s = 0.0f;
    for (int c0 = 0; c0 < DDIM; c0 += 32) {
        #pragma unroll
        for (int i = tid; i < 128 * 32; i += 128) {
            int rr = i >> 5;
            int cc = i & 31;
            tile[rr][cc] = src[(size_t)(r0 + rr) * DDIM + c0 + cc];
        }
        __syncthreads();
        #pragma unroll
        for (int cc = 0; cc < 32; cc++) {
            float v = tile[tid][cc];
            s = __fadd_rn(s, __fmul_rn(v, v));
        }
        __syncthreads();
    }
    return s;
}

__global__ void __launch_bounds__(128)
vq_xsq_kernel(const float* __restrict__ src) {
    __shared__ float tile[128][33];
    int r0 = blockIdx.x * 128;
    float s = sqsum_row_body(src, tile, threadIdx.x, r0);
    g_xsq[r0 + threadIdx.x] = s;
}

__global__ void __launch_bounds__(128)
vq_cbsq_kernel(const float* __restrict__ src) {
    __shared__ float tile[128][33];
    int r0 = blockIdx.x * 128;
    float s = sqsum_row_body(src, tile, threadIdx.x, r0);
    g_cbsq[r0 + threadIdx.x] = s;
}

// ---------------------------------------------------------------------------
// kernel 2: int8 quantization, one warp per row.
//   q = rint(v/s), s = amax/127 -> |v - s q| <= s/2 (round to nearest).
// ---------------------------------------------------------------------------
__device__ __forceinline__ void quant_row(const float* __restrict__ src,
                                          int8_t* __restrict__ dst, int row,
                                          int lane, float& s_out, float& sab_out) {
    const float* r = src + (size_t)row * DDIM + lane * 16;
    float4 v[4];
    #pragma unroll
    for (int j = 0; j < 4; j++) v[j] = *reinterpret_cast<const float4*>(r + j * 4);
    float amax = 0.0f, sab = 0.0f;
    #pragma unroll
    for (int j = 0; j < 4; j++) {
        amax = fmaxf(amax, fmaxf(fmaxf(fabsf(v[j].x), fabsf(v[j].y)),
                                 fmaxf(fabsf(v[j].z), fabsf(v[j].w))));
        sab += fabsf(v[j].x) + fabsf(v[j].y) + fabsf(v[j].z) + fabsf(v[j].w);
    }
    #pragma unroll
    for (int m = 16; m; m >>= 1) {
        amax = fmaxf(amax, __shfl_xor_sync(0xFFFFFFFFu, amax, m));
        sab += __shfl_xor_sync(0xFFFFFFFFu, sab, m);
    }
    float s = fmaxf(amax, 1e-30f) * (1.0f / 127.0f);
    float inv = 1.0f / s;
    char qb[16];
    #pragma unroll
    for (int j = 0; j < 4; j++) {
        int q0 = max(-127, min(127, __float2int_rn(v[j].x * inv)));
        int q1 = max(-127, min(127, __float2int_rn(v[j].y * inv)));
        int q2 = max(-127, min(127, __float2int_rn(v[j].z * inv)));
        int q3 = max(-127, min(127, __float2int_rn(v[j].w * inv)));
        qb[j * 4 + 0] = (char)q0; qb[j * 4 + 1] = (char)q1;
        qb[j * 4 + 2] = (char)q2; qb[j * 4 + 3] = (char)q3;
    }
    *reinterpret_cast<uint4*>(dst + (size_t)row * DDIM + lane * 16) =
        *reinterpret_cast<uint4*>(qb);
    s_out = s; sab_out = sab;
}

__global__ void __launch_bounds__(256)
vq_quant_z_kernel(const float* __restrict__ z) {
    int row = blockIdx.x * 8 + (threadIdx.x >> 5);
    int lane = threadIdx.x & 31;
    float s, sab;
    quant_row(z, g_zq, row, lane, s, sab);
    if (lane == 0) { g_sx[row] = s; g_sax[row] = sab; }
}

__global__ void __launch_bounds__(256)
vq_quant_cb_kernel(const float* __restrict__ cb) {
    int row = blockIdx.x * 8 + (threadIdx.x >> 5);
    int lane = threadIdx.x & 31;
    float s, sab;
    quant_row(cb, g_cbq, row, lane, s, sab);
    if (lane == 0) {
        g_sc[row] = s;
        atomicMax(&g_ecmax_bits, __float_as_uint(s));       // positive floats
        atomicMax(&g_csum_bits, __float_as_uint(sab));
    }
}

// ---------------------------------------------------------------------------
// kernel 3: per-row guaranteed margin
//   E = ec*sum|x| + ex*max_k sum|c| + 4*512*ex*ec  (worst-case int8 dot err)
//   M = 2*ulp(xsq) + 2*E + fp-slack
// ---------------------------------------------------------------------------
__global__ void __launch_bounds__(256)
vq_marg_kernel() {
    int row = blockIdx.x * 256 + threadIdx.x;
    float ec = __uint_as_float(g_ecmax_bits) * 0.5f;
    float csum = __uint_as_float(g_csum_bits);
    float ex = g_sx[row] * 0.5f;
    float E = ec * g_sax[row] + ex * csum + 2048.0f * ex * ec;
    float xsq = g_xsq[row];
    unsigned int u = __float_as_uint(xsq);
    int e = (int)((u >> 23) & 0xFF);
    float ulp = __uint_as_float((unsigned int)(e - 23) << 23);
    g_marg[row] = 2.0f * ulp + 2.0f * E + 2.5e-4f;
}

// ---------------------------------------------------------------------------
// kernel 4: int8 MMA GEMM (m16n8k32, s32 acc) + candidate epilogue.
//   Same warp layout / smem addressing as the twice-passing bf16 kernel,
//   scaled to bytes (s8 k32 fragment == bf16 k16 fragment pattern x2 bytes).
// ---------------------------------------------------------------------------
__global__ void __launch_bounds__(256, 1)
vq_mma_kernel() {
    extern __shared__ char dsm[];
    char* Asm = dsm;
    char* Bsm = dsm + A_BYTES;
    float* s_rowmin = reinterpret_cast<float*>(dsm + A_BYTES + B_BYTES); // [TM][4]
    float* s_thr = reinterpret_cast<float*>(dsm + A_BYTES + B_BYTES + TM * 16);

    const int tid = threadIdx.x;
    const int lane = tid & 31;
    const int wid = tid >> 5;
    const int warp_m = wid >> 2;   // 0..1
    const int warp_n = wid & 3;    // 0..3
    const int m0 = blockIdx.y * TM;
    const int k0 = blockIdx.x * TN;

    const uint32_t AbaseS = smem_to_u32(Asm);
    const uint32_t BbaseS = smem_to_u32(Bsm);

    int acc[4][4][4];
    #pragma unroll
    for (int mi = 0; mi < 4; mi++)
        #pragma unroll
        for (int ni = 0; ni < 4; ni++)
            #pragma unroll
            for (int j = 0; j < 4; j++) acc[mi][ni][j] = 0;

    issue_stage(AbaseS, BbaseS, tid, m0, k0, 0, 0);
    issue_stage(AbaseS, BbaseS, tid, m0, k0, 1, 1);
    issue_stage(AbaseS, BbaseS, tid, m0, k0, 2, 2);

    #pragma unroll 1
    for (int ch = 0; ch < NCHUNK; ch++) {
        if (ch < NCHUNK - 2) {
            asm volatile("cp.async.wait_group 2;");
        } else if (ch == NCHUNK - 2) {
            asm volatile("cp.async.wait_group 1;");
        } else {
            asm volatile("cp.async.wait_group 0;");
        }
        __syncthreads();

        if (ch + 3 < NCHUNK) {
            issue_stage(AbaseS, BbaseS, tid, m0, k0, (ch + 3) & 3, ch + 3);
        }

        const uint32_t Ab = AbaseS + (uint32_t)(ch & 3) * ABUF;
        const uint32_t Bb = BbaseS + (uint32_t)(ch & 3) * ABUF;

        #pragma unroll
        for (int kst = 0; kst < 2; kst++) {          // two k32 steps per 64B chunk
            uint32_t afr[4][4];
            #pragma unroll
            for (int mi = 0; mi < 4; mi++) {
                uint32_t addr = Ab +
                    (uint32_t)((warp_m * 64 + mi * 16 + (lane & 15)) * ROWPB +
                               kst * 32 + (lane >> 4) * 16);
                ldmx4(afr[mi][0], afr[mi][1], afr[mi][2], afr[mi][3], addr);
            }
            uint32_t bfr[2][4];
            #pragma unroll
            for (int nj = 0; nj < 2; nj++) {
                int nrow = warp_n * 32 + nj * 16 + (lane & 7) + ((lane >> 4) & 1) * 8;
                int kcol = kst * 32 + ((lane >> 3) & 1) * 16;
                uint32_t addr = Bb + (uint32_t)(nrow * ROWPB + kcol);
                ldmx4(bfr[nj][0], bfr[nj][1], bfr[nj][2], bfr[nj][3], addr);
            }
            #pragma unroll
            for (int mi = 0; mi < 4; mi++)
                #pragma unroll
                for (int ni = 0; ni < 4; ni++)
                    mma16832(acc[mi][ni], afr[mi], &bfr[ni >> 1][(ni & 1) * 2]);
        }
        __syncthreads();
    }

    // ---- epilogue: scores = (cbsq+xsq) + 2*sx*sc*idot ----
    float xs[8], sxr[8];
    #pragma unroll
    for (int mi = 0; mi < 4; mi++) {
        int r0 = m0 + warp_m * 64 + mi * 16 + (lane >> 2);
        xs[mi * 2 + 0] = g_xsq[r0];       sxr[mi * 2 + 0] = g_sx[r0];
        xs[mi * 2 + 1] = g_xsq[r0 + 8];   sxr[mi * 2 + 1] = g_sx[r0 + 8];
    }
    float cbq[8], scq[8];
    #pragma unroll
    for (int ni = 0; ni < 4; ni++) {
        int kk = k0 + warp_n * 32 + ni * 8 + (lane & 3) * 2;
        cbq[ni * 2 + 0] = g_cbsq[kk];     scq[ni * 2 + 0] = g_sc[kk];
        cbq[ni * 2 + 1] = g_cbsq[kk + 1]; scq[ni * 2 + 1] = g_sc[kk + 1];
    }
    float fsc[4][4][4];
    #pragma unroll
    for (int mi = 0; mi < 4; mi++) {
        float rmin0 = __int_as_float(0x7F800000);
        float rmin1 = __int_as_float(0x7F800000);
        float t0 = 2.0f * sxr[mi * 2 + 0];
        float t1 = 2.0f * sxr[mi * 2 + 1];
        #pragma unroll
        for (int ni = 0; ni < 4; ni++) {
            float s0 = (cbq[ni*2+0] + xs[mi*2])   + (t0 * scq[ni*2+0]) * (float)acc[mi][ni][0];
            float s1 = (cbq[ni*2+1] + xs[mi*2])   + (t0 * scq[ni*2+1]) * (float)acc[mi][ni][1];
            float s2 = (cbq[ni*2+0] + xs[mi*2+1]) + (t1 * scq[ni*2+0]) * (float)acc[mi][ni][2];
            float s3 = (cbq[ni*2+1] + xs[mi*2+1]) + (t1 * scq[ni*2+1]) * (float)acc[mi][ni][3];
            fsc[mi][ni][0] = s0; fsc[mi][ni][1] = s1;
            fsc[mi][ni][2] = s2; fsc[mi][ni][3] = s3;
            rmin0 = fminf(rmin0, fminf(s0, s1));
            rmin1 = fminf(rmin1, fminf(s2, s3));
        }
        #pragma unroll
        for (int m = 1; m <= 2; m <<= 1) {
            rmin0 = fminf(rmin0, __shfl_xor_sync(0xFFFFFFFFu, rmin0, m));
            rmin1 = fminf(rmin1, __shfl_xor_sync(0xFFFFFFFFu, rmin1, m));
        }
        if ((lane & 3) == 0) {
            s_rowmin[(warp_m * 64 + mi * 16 + (lane >> 2)) * 4 + warp_n] = rmin0;
            s_rowmin[(warp_m * 64 + mi * 16 + (lane >> 2) + 8) * 4 + warp_n] = rmin1;
        }
    }
    __syncthreads();
    if (tid < TM) {
        float g = fminf(fminf(s_rowmin[tid * 4 + 0], s_rowmin[tid * 4 + 1]),
                        fminf(s_rowmin[tid * 4 + 2], s_rowmin[tid * 4 + 3]));
        atomicMin((int*)&g_amin[m0 + tid], __float_as_int(g));  // scores > 0
        s_thr[tid] = g + g_marg[m0 + tid];
    }
    __syncthreads();

    // candidate push
    #pragma unroll
    for (int mi = 0; mi < 4; mi++) {
        #pragma unroll
        for (int h = 0; h < 2; h++) {
            int row = warp_m * 64 + mi * 16 + (lane >> 2) + h * 8;
            float thr = s_thr[row];
            int grow = m0 + row;
            #pragma unroll
            for (int ni = 0; ni < 4; ni++) {
                #pragma unroll
                for (int c = 0; c < 2; c++) {
                    float s = fsc[mi][ni][h * 2 + c];
                    if (s <= thr) {
                        int k = k0 + warp_n * 32 + ni * 8 + (lane & 3) * 2 + c;
                        int slot = atomicAdd(&g_cnt[grow], 1);
                        if (slot < CSLOTS) {
                            g_cand[(size_t)grow * CSLOTS + slot] =
                                ((unsigned long long)__float_as_uint(s) << 32) |
                                (unsigned int)k;
                        } else {
                            g_ovf[grow] = 1;
                        }
                    }
                }
            }
        }
    }
}

// ---------------------------------------------------------------------------
// kernel 5: filter candidates vs global approx min; exact fp32 rescan
// ---------------------------------------------------------------------------
__global__ void __launch_bounds__(256)
vq_filter_kernel(const float* __restrict__ z, const float* __restrict__ cb) {
    const int row = blockIdx.x * 8 + (threadIdx.x >> 5);
    const int lane = threadIdx.x & 31;
    const float thr = g_amin[row] + g_marg[row];
    int cnt = g_cnt[row];
    if (cnt > CSLOTS) cnt = CSLOTS;
    const float* zr = z + (size_t)row * DDIM;
    for (int i = lane; i < cnt; i += 32) {
        unsigned long long e = g_cand[(size_t)row * CSLOTS + i];
        float s = __uint_as_float((unsigned int)(e >> 32));
        if (s <= thr) {
            int k = (int)(e & 0xFFFFFFFFu);
            unsigned long long p = exact_pack(zr, cb + (size_t)k * DDIM, row, k);
            atomicMin(&g_minpair[row], p);
        }
    }
}

// ---------------------------------------------------------------------------
// kernel 6: overflow fallback — full exact scan (expected: zero rows)
// ---------------------------------------------------------------------------
__global__ void __launch_bounds__(256)
vq_ovf_kernel(const float* __restrict__ z, const float* __restrict__ cb) {
    const int row = blockIdx.x * 8 + (threadIdx.x >> 5);
    const int lane = threadIdx.x & 31;
    if (!g_ovf[row]) return;
    const float* zr = z + (size_t)row * DDIM;
    for (int k = lane; k < KCODES; k += 32) {
        unsigned long long p = exact_pack(zr, cb + (size_t)k * DDIM, row, k);
        atomicMin(&g_minpair[row], p);
    }
}

// ---------------------------------------------------------------------------
// kernel 7: gather codes (twice) + write idx as float
// ---------------------------------------------------------------------------
__global__ void vq_gather_kernel(const float* __restrict__ cb,
                                 float* __restrict__ out) {
    int row = blockIdx.x;
    unsigned long long pair = g_minpair[row];
    unsigned int k = (unsigned int)(pair & 0xFFFFFFFFu);

    const float4* src = reinterpret_cast<const float4*>(cb + (size_t)k * DDIM);
    float4* o1 = reinterpret_cast<float4*>(out + (size_t)row * DDIM);
    float4* o2 = reinterpret_cast<float4*>(out + BND_ELEMS + (size_t)row * DDIM);
    float4 v = src[threadIdx.x];
    o1[threadIdx.x] = v;
    o2[threadIdx.x] = v;
    if (threadIdx.x == 0) {
        out[2 * BND_ELEMS + (size_t)row] = (float)k;
    }
}

// ---------------------------------------------------------------------------
// launch
// ---------------------------------------------------------------------------
extern "C" void kernel_launch(void* const* d_in, const int* in_sizes, int n_in,
                              void* d_out, int out_size) {
    (void)out_size;
    const float* z  = (const float*)d_in[0];
    const float* cb = (const float*)d_in[1];
    if (n_in >= 2 && in_sizes[0] < in_sizes[1]) {
        const float* t = z; z = cb; cb = t;
    }
    float* out = (float*)d_out;

    cudaFuncSetAttribute(vq_mma_kernel,
                         cudaFuncAttributeMaxDynamicSharedMemorySize, SMEM_MMA);

    vq_init_kernel<<<NROWS / 256, 256>>>();
    vq_cbsq_kernel<<<KCODES / 128, 128>>>(cb);
    vq_xsq_kernel<<<NROWS / 128, 128>>>(z);
    vq_quant_z_kernel<<<NROWS / 8, 256>>>(z);
    vq_quant_cb_kernel<<<KCODES / 8, 256>>>(cb);
    vq_marg_kernel<<<NROWS / 256, 256>>>();

    dim3 grid(KCODES / TN, NROWS / TM);   // (64, 256)
    vq_mma_kernel<<<grid, 256, SMEM_MMA>>>();

    vq_filter_kernel<<<NROWS / 8, 256>>>(z, cb);
    vq_ovf_kernel<<<NROWS / 8, 256>>>(z, cb);
    vq_gather_kernel<<<NROWS, 128>>>(cb, out);
}